// round 7
// baseline (speedup 1.0000x reference)
#include <cuda_runtime.h>

#define BN   16
#define CN   80
#define HN   128
#define WN   128
#define HWN  (HN*WN)
#define NPLANES (BN*CN)
#define TOPK 100
#define NB1  2048
#define PCAP 4096                   // per-plane candidate cap (hard bound 4096)
#define SCAP 2048                   // per-batch survivor cap (expected ~740)
#define NSLICE 16                   // filter blocks per batch
#define NEG_INF __int_as_float(0xff800000)

// ---- scratch (device globals; allocation-free contract) ----
__device__ unsigned long long g_cand[NPLANES][PCAP];  // packed (valbits<<32)|~idx
__device__ int g_pcnt[NPLANES];
__device__ unsigned long long g_surv[BN][SCAP];
// zeroed each call via one memset: [BN*NB1 hist | BN scnt | BN done]
__device__ int g_zeroed[BN*NB1 + 2*BN];
#define HIST(b,i) g_zeroed[(b)*NB1 + (i)]
#define SCNT(b)   g_zeroed[BN*NB1 + (b)]
#define DONE(b)   g_zeroed[BN*NB1 + BN + (b)]

__device__ __forceinline__ int bin1f(float v){
    int b = (int)(v * 2048.0f);
    return b < 0 ? 0 : (b > NB1-1 ? NB1-1 : b);
}

// Horizontal 3-max of a row held as float4-per-lane (32 lanes cover 128 cols).
__device__ __forceinline__ float4 hmax4(float4 v, int lane){
    float left  = __shfl_up_sync(0xffffffffu, v.w, 1);
    float right = __shfl_down_sync(0xffffffffu, v.x, 1);
    left  = (lane == 0)  ? NEG_INF : left;
    right = (lane == 31) ? NEG_INF : right;
    float4 h;
    h.x = fmaxf(fmaxf(left, v.x), v.y);
    h.y = fmaxf(fmaxf(v.x, v.y), v.z);
    h.z = fmaxf(fmaxf(v.y, v.z), v.w);
    h.w = fmaxf(fmaxf(v.z, v.w), right);
    return h;
}

// Emit any of the 4 lane-columns equal to the 3x3 window max. Single guard:
// cold path for ~83% of (thread,row) pairs. No warp collectives inside.
__device__ __forceinline__ void emit_row(float4 v, float4 hp, float4 hc, float4 hn,
                                         int r, int lane, int ch,
                                         int* scnt, int* shist,
                                         unsigned long long* dst){
    float wm0 = fmaxf(fmaxf(hp.x, hc.x), hn.x);
    float wm1 = fmaxf(fmaxf(hp.y, hc.y), hn.y);
    float wm2 = fmaxf(fmaxf(hp.z, hc.z), hn.z);
    float wm3 = fmaxf(fmaxf(hp.w, hc.w), hn.w);
    bool k0 = (v.x == wm0), k1 = (v.y == wm1), k2 = (v.z == wm2), k3 = (v.w == wm3);
    if (k0 | k1 | k2 | k3){
        #pragma unroll
        for (int e = 0; e < 4; ++e){
            bool  ke = (e==0)?k0:(e==1)?k1:(e==2)?k2:k3;
            float vv = (e==0)?v.x:(e==1)?v.y:(e==2)?v.z:v.w;
            if (ke){
                int pos = atomicAdd(scnt, 1);
                if (pos < PCAP){
                    unsigned vb  = __float_as_uint(vv);
                    unsigned idx = (unsigned)(ch*HWN + r*WN + lane*4 + e);
                    dst[pos] = ((unsigned long long)vb << 32) | (unsigned)(~idx);
                }
                atomicAdd(&shist[bin1f(vv)], 1);
            }
        }
    }
}

// K1: 3x3 NMS, register-rolling separable max. One block per plane (1280).
// 8 warps x 16 rows; lane owns 4 columns. Branch-free 15-iter main loop.
__global__ __launch_bounds__(256) void nms_kernel(const float* __restrict__ hm){
    __shared__ int shist[NB1];
    __shared__ int scnt;
    const int plane = blockIdx.x;
    const int b  = plane / CN;
    const int ch = plane % CN;
    const int wid  = threadIdx.x >> 5;
    const int lane = threadIdx.x & 31;
    const int r0 = wid * 16;
    const float* base = hm + (size_t)plane * HWN + lane*4;

    if (threadIdx.x == 0) scnt = 0;
    for (int i = threadIdx.x; i < NB1; i += 256) shist[i] = 0;
    __syncthreads();

    unsigned long long* dst = g_cand[plane];

    float4 v_cur, v_next, h_prev, h_cur, h_next;
    if (r0 > 0){
        h_prev = hmax4(*(const float4*)(base + (size_t)(r0-1)*WN), lane);
    } else {
        h_prev = make_float4(NEG_INF, NEG_INF, NEG_INF, NEG_INF);
    }
    v_cur = *(const float4*)(base + (size_t)r0*WN);
    h_cur = hmax4(v_cur, lane);

    // rows r0 .. r0+14: next row (<= r0+15) always in-bounds for all warps
    #pragma unroll 3
    for (int r = r0; r < r0 + 15; ++r){
        v_next = *(const float4*)(base + (size_t)(r+1)*WN);
        h_next = hmax4(v_next, lane);
        emit_row(v_cur, h_prev, h_cur, h_next, r, lane, ch, &scnt, shist, dst);
        h_prev = h_cur; h_cur = h_next; v_cur = v_next;
    }
    // final row r0+15: only warp 7's next row (128) is out of bounds
    if (r0 + 16 < HN){
        h_next = hmax4(*(const float4*)(base + (size_t)(r0+16)*WN), lane);
    } else {
        h_next = make_float4(NEG_INF, NEG_INF, NEG_INF, NEG_INF);
    }
    emit_row(v_cur, h_prev, h_cur, h_next, r0+15, lane, ch, &scnt, shist, dst);

    __syncthreads();
    if (threadIdx.x == 0) g_pcnt[plane] = (scnt > PCAP) ? PCAP : scnt;
    for (int i = threadIdx.x; i < NB1; i += 256){
        int c = shist[i];
        if (c) atomicAdd(&HIST(b, i), c);
    }
}

// K2: per-batch threshold (suffix scan) + survivor compaction; the LAST
// finishing block of each batch ranks + decodes inline.
// grid = (NSLICE, BN), 512 threads.
// NOTE: every __ballot_sync loop below has a UNIFORM trip count — all threads
// of the block execute every iteration; validity is folded into the predicate.
__global__ __launch_bounds__(512) void filter_rank_kernel(const float* __restrict__ offset,
                                                          const float* __restrict__ wh,
                                                          float* __restrict__ out){
    __shared__ int s0[NB1], s1[NB1];
    __shared__ int sB1, sLast;
    __shared__ unsigned long long sv[SCAP];   // used only by the last block
    const int b   = blockIdx.y;
    const int tid = threadIdx.x;

    // threshold bin from global histogram
    for (int i = tid; i < NB1; i += 512) s0[i] = HIST(b, i);
    __syncthreads();
    int* A = s0; int* B = s1;
    for (int off = 1; off < NB1; off <<= 1){
        for (int i = tid; i < NB1; i += 512)
            B[i] = A[i] + ((i + off < NB1) ? A[i + off] : 0);
        __syncthreads();
        int* t = A; A = B; B = t;
    }
    for (int i = tid; i < NB1; i += 512)
        if (A[i] >= TOPK && (i == NB1-1 || A[i+1] < TOPK)) sB1 = i;
    __syncthreads();
    const int b1 = sB1;

    // compact survivors from this block's plane slices (uniform-trip ballots)
    const int lane = tid & 31;
    const unsigned lmask = (1u << lane) - 1u;
    unsigned long long* svg = g_surv[b];
    for (int p = blockIdx.x; p < CN; p += NSLICE){
        const int plane = b*CN + p;
        const int cnt = g_pcnt[plane];
        const unsigned long long* src = g_cand[plane];
        for (int i0 = 0; i0 < cnt; i0 += 512){
            const int i = i0 + tid;
            const bool valid = (i < cnt);
            unsigned long long kk = valid ? src[i] : 0ull;
            float v = __uint_as_float((unsigned)(kk >> 32));
            bool take = valid && (bin1f(v) >= b1);
            unsigned bal = __ballot_sync(0xffffffffu, take);
            int wb = 0;
            if (lane == 0 && bal) wb = atomicAdd(&SCNT(b), __popc(bal));
            wb = __shfl_sync(0xffffffffu, wb, 0);
            if (take){
                int pos = wb + __popc(bal & lmask);
                if (pos < SCAP) svg[pos] = kk;
            }
        }
    }

    // last-done block of this batch performs rank + decode
    __threadfence();
    __syncthreads();
    if (tid == 0) sLast = (atomicAdd(&DONE(b), 1) == NSLICE - 1);
    __syncthreads();
    if (!sLast) return;

    int m = SCNT(b); if (m > SCAP) m = SCAP;
    for (int i = tid; i < m; i += 512) sv[i] = svg[i];
    __syncthreads();

    for (int e = tid; e < m; e += 512){
        unsigned long long key = sv[e];
        int rank = 0;
        for (int j = 0; j < m; ++j) rank += (sv[j] > key);
        if (rank < TOPK){
            unsigned vb = (unsigned)(key >> 32);
            int idx = (int)(~(unsigned)key);
            float score = __uint_as_float(vb);
            int chn = idx / HWN;
            int spatial = idx - chn*HWN;
            int ys = spatial >> 7, xs = spatial & (WN-1);
            const float* offb = offset + (size_t)b * 2 * HWN;
            const float* whb  = wh     + (size_t)b * 2 * HWN;
            float ox = offb[spatial], oy = offb[HWN + spatial];
            float ww = whb[spatial],  hh = whb[HWN + spatial];
            float cx = (float)xs + ox, cy = (float)ys + oy;
            float hw2 = ww * 0.5f, hh2 = hh * 0.5f;

            float* out_ids = out;                 // (B,100,1)
            float* out_sc  = out + BN*TOPK;       // (B,100,1)
            float* out_bb  = out + 2*BN*TOPK;     // (B,100,4)
            out_ids[b*TOPK + rank] = (float)chn;
            out_sc [b*TOPK + rank] = score;
            float* bbp = out_bb + (size_t)(b*TOPK + rank)*4;
            bbp[0] = (cx - hw2)*4.0f;
            bbp[1] = (cy - hh2)*4.0f;
            bbp[2] = (cx + hw2)*4.0f;
            bbp[3] = (cy + hh2)*4.0f;
        }
    }
}

extern "C" void kernel_launch(void* const* d_in, const int* in_sizes, int n_in,
                              void* d_out, int out_size){
    const float* hm     = (const float*)d_in[0];
    const float* offset = (const float*)d_in[1];
    const float* wh     = (const float*)d_in[2];
    float* out = (float*)d_out;

    void* zptr = nullptr;
    cudaGetSymbolAddress(&zptr, g_zeroed);
    cudaMemsetAsync(zptr, 0, sizeof(int)*(BN*NB1 + 2*BN));

    nms_kernel<<<NPLANES, 256>>>(hm);
    filter_rank_kernel<<<dim3(NSLICE, BN), 512>>>(offset, wh, out);
}

// round 8
// speedup vs baseline: 1.3730x; 1.3730x over previous
#include <cuda_runtime.h>

#define BN   16
#define CN   80
#define HN   128
#define WN   128
#define HWN  (HN*WN)
#define NPLANES (BN*CN)
#define TOPK 100
#define NB1  2048
#define SBUF 3072                   // shared candidate cap per plane (expected ~1820)
#define GCAP 1024                   // compacted per-plane global cap (expected ~130)
#define SCAP 2048                   // per-batch survivor cap (expected ~700)
#define FULLM 0xffffffffu
#define NEG_INF __int_as_float(0xff800000)

// ---- scratch (device globals; allocation-free contract) ----
__device__ unsigned long long g_cand[NPLANES][GCAP];  // compacted plane top-~100+
__device__ int g_pcnt[NPLANES];
__device__ int g_zeroed[BN*NB1];                      // batch histograms (memset)
#define HIST(b,i) g_zeroed[(b)*NB1 + (i)]

__device__ __forceinline__ int bin1f(float v){
    int b = (int)(v * 2048.0f);
    return b < 0 ? 0 : (b > NB1-1 ? NB1-1 : b);
}

// Horizontal 3-max of a row held as float4-per-lane (32 lanes cover 128 cols).
__device__ __forceinline__ float4 hmax4(float4 v, int lane){
    float left  = __shfl_up_sync(FULLM, v.w, 1);
    float right = __shfl_down_sync(FULLM, v.x, 1);
    left  = (lane == 0)  ? NEG_INF : left;
    right = (lane == 31) ? NEG_INF : right;
    float4 h;
    h.x = fmaxf(fmaxf(left, v.x), v.y);
    h.y = fmaxf(fmaxf(v.x, v.y), v.z);
    h.z = fmaxf(fmaxf(v.y, v.z), v.w);
    h.w = fmaxf(fmaxf(v.z, v.w), right);
    return h;
}

// Emit keeps: 4 ballots + ONE warp atomic + STS per row (no divergent atomics).
__device__ __forceinline__ void emit_row(float4 v, float4 hp, float4 hc, float4 hn,
                                         int r, int lane, unsigned lmask, int ch,
                                         int* scnt, unsigned long long* sbuf){
    float wm0 = fmaxf(fmaxf(hp.x, hc.x), hn.x);
    float wm1 = fmaxf(fmaxf(hp.y, hc.y), hn.y);
    float wm2 = fmaxf(fmaxf(hp.z, hc.z), hn.z);
    float wm3 = fmaxf(fmaxf(hp.w, hc.w), hn.w);
    bool k0 = (v.x == wm0), k1 = (v.y == wm1), k2 = (v.z == wm2), k3 = (v.w == wm3);
    unsigned b0 = __ballot_sync(FULLM, k0);
    unsigned b1 = __ballot_sync(FULLM, k1);
    unsigned b2 = __ballot_sync(FULLM, k2);
    unsigned b3 = __ballot_sync(FULLM, k3);
    if (b0 | b1 | b2 | b3){                            // warp-uniform branch
        int c0 = __popc(b0), c1 = __popc(b1), c2 = __popc(b2);
        int total = c0 + c1 + c2 + __popc(b3);
        int base = 0;
        if (lane == 0) base = atomicAdd(scnt, total);
        base = __shfl_sync(FULLM, base, 0);
        const unsigned ib = (unsigned)(ch*HWN + r*WN + lane*4);
        if (k0){ int p = base + __popc(b0 & lmask);
                 if (p < SBUF) sbuf[p] = ((unsigned long long)__float_as_uint(v.x) << 32) | (unsigned)(~ib); }
        if (k1){ int p = base + c0 + __popc(b1 & lmask);
                 if (p < SBUF) sbuf[p] = ((unsigned long long)__float_as_uint(v.y) << 32) | (unsigned)(~(ib+1)); }
        if (k2){ int p = base + c0 + c1 + __popc(b2 & lmask);
                 if (p < SBUF) sbuf[p] = ((unsigned long long)__float_as_uint(v.z) << 32) | (unsigned)(~(ib+2)); }
        if (k3){ int p = base + c0 + c1 + c2 + __popc(b3 & lmask);
                 if (p < SBUF) sbuf[p] = ((unsigned long long)__float_as_uint(v.w) << 32) | (unsigned)(~(ib+3)); }
    }
}

// Warp-serial suffix scan from top bin: returns largest bin with suffix >= TOPK
// (0 if none). Call from ONE full warp; hist read via rd(i).
// K1: 3x3 NMS, register-rolling separable max + per-plane top-100 cut.
__global__ __launch_bounds__(256) void nms_kernel(const float* __restrict__ hm){
    __shared__ unsigned long long sbuf[SBUF];
    __shared__ int shist[NB1];
    __shared__ int scnt, scnt2, sCut;
    const int plane = blockIdx.x;
    const int b  = plane / CN;
    const int ch = plane % CN;
    const int wid  = threadIdx.x >> 5;
    const int lane = threadIdx.x & 31;
    const unsigned lmask = (1u << lane) - 1u;
    const int r0 = wid * 16;
    const float* base = hm + (size_t)plane * HWN + lane*4;

    if (threadIdx.x == 0){ scnt = 0; scnt2 = 0; sCut = 0; }
    __syncthreads();

    float4 v_cur, v_next, h_prev, h_cur, h_next;
    if (r0 > 0){
        h_prev = hmax4(*(const float4*)(base + (size_t)(r0-1)*WN), lane);
    } else {
        h_prev = make_float4(NEG_INF, NEG_INF, NEG_INF, NEG_INF);
    }
    v_cur = *(const float4*)(base + (size_t)r0*WN);
    h_cur = hmax4(v_cur, lane);

    #pragma unroll 3
    for (int r = r0; r < r0 + 15; ++r){
        v_next = *(const float4*)(base + (size_t)(r+1)*WN);
        h_next = hmax4(v_next, lane);
        emit_row(v_cur, h_prev, h_cur, h_next, r, lane, lmask, ch, &scnt, sbuf);
        h_prev = h_cur; h_cur = h_next; v_cur = v_next;
    }
    if (r0 + 16 < HN){
        h_next = hmax4(*(const float4*)(base + (size_t)(r0+16)*WN), lane);
    } else {
        h_next = make_float4(NEG_INF, NEG_INF, NEG_INF, NEG_INF);
    }
    emit_row(v_cur, h_prev, h_cur, h_next, r0+15, lane, lmask, ch, &scnt, sbuf);

    // ---- end phase: per-plane histogram -> cut bin -> compact to global ----
    __syncthreads();
    const int nc = (scnt > SBUF) ? SBUF : scnt;
    for (int i = threadIdx.x; i < NB1; i += 256) shist[i] = 0;
    __syncthreads();
    for (int i = threadIdx.x; i < nc; i += 256){
        float v = __uint_as_float((unsigned)(sbuf[i] >> 32));
        atomicAdd(&shist[bin1f(v)], 1);
    }
    __syncthreads();

    if (wid == 0){                               // warp-serial cut scan from top
        int acc = 0, cut = 0;
        for (int bb = NB1 - 32; bb >= 0; bb -= 32){
            int suf = shist[bb + lane];
            #pragma unroll
            for (int off = 1; off < 32; off <<= 1){
                int t = __shfl_down_sync(FULLM, suf, off);
                if (lane + off < 32) suf += t;
            }
            unsigned bal = __ballot_sync(FULLM, acc + suf >= TOPK);
            if (bal){ cut = bb + (31 - __clz(bal)); break; }
            acc += __shfl_sync(FULLM, suf, 0);
        }
        if (lane == 0) sCut = cut;
    }
    __syncthreads();
    const int p1 = sCut;

    unsigned long long* dst = g_cand[plane];
    for (int i0 = 0; i0 < nc; i0 += 256){
        const int i = i0 + threadIdx.x;
        const bool valid = (i < nc);
        unsigned long long kk = valid ? sbuf[i] : 0ull;
        int bin = bin1f(__uint_as_float((unsigned)(kk >> 32)));
        bool take = valid && (bin >= p1);
        unsigned bal = __ballot_sync(FULLM, take);
        int wb = 0;
        if (lane == 0 && bal) wb = atomicAdd(&scnt2, __popc(bal));
        wb = __shfl_sync(FULLM, wb, 0);
        if (take){
            int pos = wb + __popc(bal & lmask);
            if (pos < GCAP){
                dst[pos] = kk;
                atomicAdd(&HIST(b, bin), 1);     // REDG, scattered
            }
        }
    }
    __syncthreads();
    if (threadIdx.x == 0) g_pcnt[plane] = (scnt2 > GCAP) ? GCAP : scnt2;
}

// K2: one block per batch. Warp-serial cut on global hist -> warp-per-plane
// compaction into shared -> O(m^2) rank -> decode. grid=BN, 1024 threads.
__global__ __launch_bounds__(1024) void filter_rank_kernel(const float* __restrict__ offset,
                                                           const float* __restrict__ wh,
                                                           float* __restrict__ out){
    __shared__ unsigned long long sv[SCAP];
    __shared__ int spcnt[CN];
    __shared__ int sB1, sCol;
    const int b    = blockIdx.x;
    const int tid  = threadIdx.x;
    const int wid  = tid >> 5;
    const int lane = tid & 31;
    const unsigned lmask = (1u << lane) - 1u;

    if (tid == 0){ sB1 = 0; sCol = 0; }
    if (tid < CN) spcnt[tid] = g_pcnt[b*CN + tid];
    if (wid == 0){                               // warp-serial cut scan (global)
        int acc = 0, cut = 0;
        for (int bb = NB1 - 32; bb >= 0; bb -= 32){
            int suf = HIST(b, bb + lane);
            #pragma unroll
            for (int off = 1; off < 32; off <<= 1){
                int t = __shfl_down_sync(FULLM, suf, off);
                if (lane + off < 32) suf += t;
            }
            unsigned bal = __ballot_sync(FULLM, acc + suf >= TOPK);
            if (bal){ cut = bb + (31 - __clz(bal)); break; }
            acc += __shfl_sync(FULLM, suf, 0);
        }
        if (lane == 0) sB1 = cut;
    }
    __syncthreads();
    const int b1 = sB1;

    // warp w compacts planes w, w+32, w+64 (independent -> latency overlap)
    for (int p = wid; p < CN; p += 32){
        const int cnt = spcnt[p];
        const unsigned long long* src = g_cand[b*CN + p];
        for (int i0 = 0; i0 < cnt; i0 += 32){
            const int i = i0 + lane;
            const bool valid = (i < cnt);
            unsigned long long kk = valid ? src[i] : 0ull;
            float v = __uint_as_float((unsigned)(kk >> 32));
            bool take = valid && (bin1f(v) >= b1);
            unsigned bal = __ballot_sync(FULLM, take);
            int wb = 0;
            if (lane == 0 && bal) wb = atomicAdd(&sCol, __popc(bal));
            wb = __shfl_sync(FULLM, wb, 0);
            if (take){
                int pos = wb + __popc(bal & lmask);
                if (pos < SCAP) sv[pos] = kk;
            }
        }
    }
    __syncthreads();
    const int m = (sCol > SCAP) ? SCAP : sCol;

    for (int e = tid; e < m; e += 1024){
        unsigned long long key = sv[e];
        int rank = 0;
        for (int j = 0; j < m; ++j) rank += (sv[j] > key);
        if (rank < TOPK){
            unsigned vb = (unsigned)(key >> 32);
            int idx = (int)(~(unsigned)key);
            float score = __uint_as_float(vb);
            int chn = idx / HWN;
            int spatial = idx - chn*HWN;
            int ys = spatial >> 7, xs = spatial & (WN-1);
            const float* offb = offset + (size_t)b * 2 * HWN;
            const float* whb  = wh     + (size_t)b * 2 * HWN;
            float ox = offb[spatial], oy = offb[HWN + spatial];
            float ww = whb[spatial],  hh = whb[HWN + spatial];
            float cx = (float)xs + ox, cy = (float)ys + oy;
            float hw2 = ww * 0.5f, hh2 = hh * 0.5f;

            float* out_ids = out;                 // (B,100,1)
            float* out_sc  = out + BN*TOPK;       // (B,100,1)
            float* out_bb  = out + 2*BN*TOPK;     // (B,100,4)
            out_ids[b*TOPK + rank] = (float)chn;
            out_sc [b*TOPK + rank] = score;
            float* bbp = out_bb + (size_t)(b*TOPK + rank)*4;
            bbp[0] = (cx - hw2)*4.0f;
            bbp[1] = (cy - hh2)*4.0f;
            bbp[2] = (cx + hw2)*4.0f;
            bbp[3] = (cy + hh2)*4.0f;
        }
    }
}

extern "C" void kernel_launch(void* const* d_in, const int* in_sizes, int n_in,
                              void* d_out, int out_size){
    const float* hm     = (const float*)d_in[0];
    const float* offset = (const float*)d_in[1];
    const float* wh     = (const float*)d_in[2];
    float* out = (float*)d_out;

    void* zptr = nullptr;
    cudaGetSymbolAddress(&zptr, g_zeroed);
    cudaMemsetAsync(zptr, 0, sizeof(int)*(BN*NB1));

    nms_kernel<<<NPLANES, 256>>>(hm);
    filter_rank_kernel<<<BN, 1024>>>(offset, wh, out);
}

// round 9
// speedup vs baseline: 1.6917x; 1.2321x over previous
#include <cuda_runtime.h>

#define BN   16
#define CN   80
#define HN   128
#define WN   128
#define HWN  (HN*WN)
#define NPLANES (BN*CN)
#define TOPK 100
#define NB1  2048
#define SBUF 3072                   // shared candidate cap per plane (expected ~1820)
#define GCAP 1024                   // compacted per-plane global cap (expected ~130)
#define SCAP 2048                   // per-batch survivor cap (expected ~700)
#define RCAP 1024                   // refined cap (expected ~101)
#define FULLM 0xffffffffu
#define NEG_INF __int_as_float(0xff800000)

// ---- scratch (device globals; allocation-free contract; no zeroing needed) ----
__device__ unsigned long long g_cand[NPLANES][GCAP];  // compacted plane top-~100+
__device__ int g_pcnt[NPLANES];                       // written unconditionally

__device__ __forceinline__ int bin1f(float v){
    int b = (int)(v * 2048.0f);
    return b < 0 ? 0 : (b > NB1-1 ? NB1-1 : b);
}
__device__ __forceinline__ int bin2f(float v, int b1){
    float f = v * 2048.0f - (float)b1;
    int b = (int)(f * 2048.0f);
    return b < 0 ? 0 : (b > NB1-1 ? NB1-1 : b);
}

// Warp-serial suffix cut scan from the top: largest bin with initAcc+suffix>=TOPK.
// Call from one full warp. Returns cut via lane 0.
__device__ __forceinline__ int cut_scan(const int* histArr, int initAcc, int lane){
    int acc = initAcc, cut = 0;
    for (int bb = NB1 - 32; bb >= 0; bb -= 32){
        int suf = histArr[bb + lane];
        #pragma unroll
        for (int off = 1; off < 32; off <<= 1){
            int t = __shfl_down_sync(FULLM, suf, off);
            if (lane + off < 32) suf += t;
        }
        unsigned bal = __ballot_sync(FULLM, acc + suf >= TOPK);
        if (bal){ cut = bb + (31 - __clz(bal)); break; }
        acc += __shfl_sync(FULLM, suf, 0);
    }
    return cut;
}

// Horizontal 3-max of a row held as float4-per-lane (32 lanes cover 128 cols).
__device__ __forceinline__ float4 hmax4(float4 v, int lane){
    float left  = __shfl_up_sync(FULLM, v.w, 1);
    float right = __shfl_down_sync(FULLM, v.x, 1);
    left  = (lane == 0)  ? NEG_INF : left;
    right = (lane == 31) ? NEG_INF : right;
    float4 h;
    h.x = fmaxf(fmaxf(left, v.x), v.y);
    h.y = fmaxf(fmaxf(v.x, v.y), v.z);
    h.z = fmaxf(fmaxf(v.y, v.z), v.w);
    h.w = fmaxf(fmaxf(v.z, v.w), right);
    return h;
}

// Emit keeps: 4 ballots + ONE warp atomic + STS per row (no divergent atomics).
__device__ __forceinline__ void emit_row(float4 v, float4 hp, float4 hc, float4 hn,
                                         int r, int lane, unsigned lmask, int ch,
                                         int* scnt, unsigned long long* sbuf){
    float wm0 = fmaxf(fmaxf(hp.x, hc.x), hn.x);
    float wm1 = fmaxf(fmaxf(hp.y, hc.y), hn.y);
    float wm2 = fmaxf(fmaxf(hp.z, hc.z), hn.z);
    float wm3 = fmaxf(fmaxf(hp.w, hc.w), hn.w);
    bool k0 = (v.x == wm0), k1 = (v.y == wm1), k2 = (v.z == wm2), k3 = (v.w == wm3);
    unsigned b0 = __ballot_sync(FULLM, k0);
    unsigned b1 = __ballot_sync(FULLM, k1);
    unsigned b2 = __ballot_sync(FULLM, k2);
    unsigned b3 = __ballot_sync(FULLM, k3);
    if (b0 | b1 | b2 | b3){                            // warp-uniform branch
        int c0 = __popc(b0), c1 = __popc(b1), c2 = __popc(b2);
        int total = c0 + c1 + c2 + __popc(b3);
        int base = 0;
        if (lane == 0) base = atomicAdd(scnt, total);
        base = __shfl_sync(FULLM, base, 0);
        const unsigned ib = (unsigned)(ch*HWN + r*WN + lane*4);
        if (k0){ int p = base + __popc(b0 & lmask);
                 if (p < SBUF) sbuf[p] = ((unsigned long long)__float_as_uint(v.x) << 32) | (unsigned)(~ib); }
        if (k1){ int p = base + c0 + __popc(b1 & lmask);
                 if (p < SBUF) sbuf[p] = ((unsigned long long)__float_as_uint(v.y) << 32) | (unsigned)(~(ib+1)); }
        if (k2){ int p = base + c0 + c1 + __popc(b2 & lmask);
                 if (p < SBUF) sbuf[p] = ((unsigned long long)__float_as_uint(v.z) << 32) | (unsigned)(~(ib+2)); }
        if (k3){ int p = base + c0 + c1 + c2 + __popc(b3 & lmask);
                 if (p < SBUF) sbuf[p] = ((unsigned long long)__float_as_uint(v.w) << 32) | (unsigned)(~(ib+3)); }
    }
}

// K1: 3x3 NMS, register-rolling separable max + per-plane top-100 cut.
__global__ __launch_bounds__(256) void nms_kernel(const float* __restrict__ hm){
    __shared__ unsigned long long sbuf[SBUF];
    __shared__ int shist[NB1];
    __shared__ int scnt, scnt2, sCut;
    const int plane = blockIdx.x;
    const int ch = plane % CN;
    const int wid  = threadIdx.x >> 5;
    const int lane = threadIdx.x & 31;
    const unsigned lmask = (1u << lane) - 1u;
    const int r0 = wid * 16;
    const float* base = hm + (size_t)plane * HWN + lane*4;

    if (threadIdx.x == 0){ scnt = 0; scnt2 = 0; sCut = 0; }
    for (int i = threadIdx.x; i < NB1; i += 256) shist[i] = 0;
    __syncthreads();

    float4 v_cur, v_next, h_prev, h_cur, h_next;
    if (r0 > 0){
        h_prev = hmax4(*(const float4*)(base + (size_t)(r0-1)*WN), lane);
    } else {
        h_prev = make_float4(NEG_INF, NEG_INF, NEG_INF, NEG_INF);
    }
    v_cur = *(const float4*)(base + (size_t)r0*WN);
    h_cur = hmax4(v_cur, lane);

    #pragma unroll 3
    for (int r = r0; r < r0 + 15; ++r){
        v_next = *(const float4*)(base + (size_t)(r+1)*WN);
        h_next = hmax4(v_next, lane);
        emit_row(v_cur, h_prev, h_cur, h_next, r, lane, lmask, ch, &scnt, sbuf);
        h_prev = h_cur; h_cur = h_next; v_cur = v_next;
    }
    if (r0 + 16 < HN){
        h_next = hmax4(*(const float4*)(base + (size_t)(r0+16)*WN), lane);
    } else {
        h_next = make_float4(NEG_INF, NEG_INF, NEG_INF, NEG_INF);
    }
    emit_row(v_cur, h_prev, h_cur, h_next, r0+15, lane, lmask, ch, &scnt, sbuf);

    // ---- end phase: per-plane histogram -> cut bin -> compact to global ----
    __syncthreads();
    const int nc = (scnt > SBUF) ? SBUF : scnt;
    for (int i = threadIdx.x; i < nc; i += 256){
        float v = __uint_as_float((unsigned)(sbuf[i] >> 32));
        atomicAdd(&shist[bin1f(v)], 1);
    }
    __syncthreads();
    if (wid == 0){
        int cut = cut_scan(shist, 0, lane);
        if (lane == 0) sCut = cut;
    }
    __syncthreads();
    const int p1 = sCut;

    unsigned long long* dst = g_cand[plane];
    for (int i0 = 0; i0 < nc; i0 += 256){
        const int i = i0 + threadIdx.x;
        const bool valid = (i < nc);
        unsigned long long kk = valid ? sbuf[i] : 0ull;
        int bin = bin1f(__uint_as_float((unsigned)(kk >> 32)));
        bool take = valid && (bin >= p1);
        unsigned bal = __ballot_sync(FULLM, take);
        int wb = 0;
        if (lane == 0 && bal) wb = atomicAdd(&scnt2, __popc(bal));
        wb = __shfl_sync(FULLM, wb, 0);
        if (take){
            int pos = wb + __popc(bal & lmask);
            if (pos < GCAP) dst[pos] = kk;
        }
    }
    __syncthreads();
    if (threadIdx.x == 0) g_pcnt[plane] = (scnt2 > GCAP) ? GCAP : scnt2;
}

// K2: one block per batch. Level-1 hist from the ~10k compacted candidates ->
// cut b1 -> compact to shared -> level-2 refine -> rank ~101 -> decode.
__global__ __launch_bounds__(1024) void filter_rank_kernel(const float* __restrict__ offset,
                                                           const float* __restrict__ wh,
                                                           float* __restrict__ out){
    __shared__ int hist[NB1];
    __shared__ unsigned long long sv[SCAP];
    __shared__ unsigned long long sv2[RCAP];
    __shared__ int spcnt[CN];
    __shared__ int sB1, sB2, sCol, sCol2, sCntHi;
    const int b    = blockIdx.x;
    const int tid  = threadIdx.x;
    const int wid  = tid >> 5;
    const int lane = tid & 31;
    const unsigned lmask = (1u << lane) - 1u;

    if (tid == 0){ sB1 = 0; sB2 = 0; sCol = 0; sCol2 = 0; sCntHi = 0; }
    for (int i = tid; i < NB1; i += 1024) hist[i] = 0;
    if (tid < CN) spcnt[tid] = g_pcnt[b*CN + tid];
    __syncthreads();

    // Pass A: level-1 histogram over this batch's compacted candidates
    for (int p = wid; p < CN; p += 32){
        const int cnt = spcnt[p];
        const unsigned long long* src = g_cand[b*CN + p];
        for (int i = lane; i < cnt; i += 32){
            float v = __uint_as_float((unsigned)(src[i] >> 32));
            atomicAdd(&hist[bin1f(v)], 1);
        }
    }
    __syncthreads();
    if (wid == 0){
        int cut = cut_scan(hist, 0, lane);
        if (lane == 0) sB1 = cut;
    }
    __syncthreads();
    const int b1 = sB1;

    // Pass B: compact survivors (bin >= b1) into shared (uniform-trip ballots)
    for (int p = wid; p < CN; p += 32){
        const int cnt = spcnt[p];
        const unsigned long long* src = g_cand[b*CN + p];
        for (int i0 = 0; i0 < cnt; i0 += 32){
            const int i = i0 + lane;
            const bool valid = (i < cnt);
            unsigned long long kk = valid ? src[i] : 0ull;
            float v = __uint_as_float((unsigned)(kk >> 32));
            bool take = valid && (bin1f(v) >= b1);
            unsigned bal = __ballot_sync(FULLM, take);
            int wb = 0;
            if (lane == 0 && bal) wb = atomicAdd(&sCol, __popc(bal));
            wb = __shfl_sync(FULLM, wb, 0);
            if (take){
                int pos = wb + __popc(bal & lmask);
                if (pos < SCAP) sv[pos] = kk;
            }
        }
    }
    __syncthreads();
    const int m = (sCol > SCAP) ? SCAP : sCol;

    // Level-2: sub-bin histogram of the bin==b1 items; cntHi = items above b1
    for (int i = tid; i < NB1; i += 1024) hist[i] = 0;
    __syncthreads();
    for (int i = tid; i < m; i += 1024){
        float v = __uint_as_float((unsigned)(sv[i] >> 32));
        int bb = bin1f(v);
        if (bb > b1) atomicAdd(&sCntHi, 1);
        else atomicAdd(&hist[bin2f(v, b1)], 1);     // bb == b1 by construction
    }
    __syncthreads();
    if (wid == 0){
        int cut = cut_scan(hist, sCntHi, lane);
        if (lane == 0) sB2 = cut;
    }
    __syncthreads();
    const int b2 = sB2;

    // Compact refined set (~101 items). Ranks within it equal global ranks.
    for (int i0 = 0; i0 < m; i0 += 1024){
        const int i = i0 + tid;
        const bool valid = (i < m);
        unsigned long long kk = valid ? sv[i] : 0ull;
        float v = __uint_as_float((unsigned)(kk >> 32));
        bool take = valid && ((bin1f(v) > b1) || (bin2f(v, b1) >= b2));
        unsigned bal = __ballot_sync(FULLM, take);
        int wb = 0;
        if (lane == 0 && bal) wb = atomicAdd(&sCol2, __popc(bal));
        wb = __shfl_sync(FULLM, wb, 0);
        if (take){
            int pos = wb + __popc(bal & lmask);
            if (pos < RCAP) sv2[pos] = kk;
        }
    }
    __syncthreads();
    const int m2 = (sCol2 > RCAP) ? RCAP : sCol2;

    for (int e = tid; e < m2; e += 1024){
        unsigned long long key = sv2[e];
        int rank = 0;
        for (int j = 0; j < m2; ++j) rank += (sv2[j] > key);
        if (rank < TOPK){
            unsigned vb = (unsigned)(key >> 32);
            int idx = (int)(~(unsigned)key);
            float score = __uint_as_float(vb);
            int chn = idx / HWN;
            int spatial = idx - chn*HWN;
            int ys = spatial >> 7, xs = spatial & (WN-1);
            const float* offb = offset + (size_t)b * 2 * HWN;
            const float* whb  = wh     + (size_t)b * 2 * HWN;
            float ox = offb[spatial], oy = offb[HWN + spatial];
            float ww = whb[spatial],  hh = whb[HWN + spatial];
            float cx = (float)xs + ox, cy = (float)ys + oy;
            float hw2 = ww * 0.5f, hh2 = hh * 0.5f;

            float* out_ids = out;                 // (B,100,1)
            float* out_sc  = out + BN*TOPK;       // (B,100,1)
            float* out_bb  = out + 2*BN*TOPK;     // (B,100,4)
            out_ids[b*TOPK + rank] = (float)chn;
            out_sc [b*TOPK + rank] = score;
            float* bbp = out_bb + (size_t)(b*TOPK + rank)*4;
            bbp[0] = (cx - hw2)*4.0f;
            bbp[1] = (cy - hh2)*4.0f;
            bbp[2] = (cx + hw2)*4.0f;
            bbp[3] = (cy + hh2)*4.0f;
        }
    }
}

extern "C" void kernel_launch(void* const* d_in, const int* in_sizes, int n_in,
                              void* d_out, int out_size){
    const float* hm     = (const float*)d_in[0];
    const float* offset = (const float*)d_in[1];
    const float* wh     = (const float*)d_in[2];
    float* out = (float*)d_out;

    nms_kernel<<<NPLANES, 256>>>(hm);
    filter_rank_kernel<<<BN, 1024>>>(offset, wh, out);
}